// round 10
// baseline (speedup 1.0000x reference)
#include <cuda_runtime.h>
#include <math.h>
#include <stdint.h>

#define Sx   256
#define Dx   128
#define Hx   8
#define DKx  16
#define NKx  16
#define BSx  4

typedef unsigned long long u64;

// ---------------- scratch ----------------
__device__ float d_Q1[BSx * Sx * Dx];
__device__ float d_V1[BSx * Sx * Dx];
__device__ float d_cat1[BSx * Sx * Dx];
__device__ float d_q4[NKx * Dx];
__device__ float d_k4[BSx * Sx * Dx];
__device__ float d_v4[BSx * Sx * Dx];
__device__ float d_cat4[BSx * NKx * Sx * Dx];
__device__ float d_WT[7][Dx * Dx];

// ---------------- helpers ----------------
__device__ __forceinline__ float warp_max(float v) {
#pragma unroll
    for (int o = 16; o; o >>= 1) v = fmaxf(v, __shfl_xor_sync(0xffffffffu, v, o));
    return v;
}
__device__ __forceinline__ float warp_sum(float v) {
#pragma unroll
    for (int o = 16; o; o >>= 1) v += __shfl_xor_sync(0xffffffffu, v, o);
    return v;
}
__device__ __forceinline__ float rcp_ap(float x) {
    float r; asm("rcp.approx.f32 %0, %1;" : "=f"(r) : "f"(x)); return r;
}
__device__ __forceinline__ float sqrt_ap(float x) {
    float r; asm("sqrt.approx.f32 %0, %1;" : "=f"(r) : "f"(x)); return r;
}
__device__ __forceinline__ float ex2_ap(float x) {
    float r; asm("ex2.approx.f32 %0, %1;" : "=f"(r) : "f"(x)); return r;
}
__device__ __forceinline__ u64 pk2(float x) {
    u64 r; asm("mov.b64 %0, {%1, %1};" : "=l"(r) : "f"(x)); return r;
}
__device__ __forceinline__ void ffma2(u64& d, u64 a, u64 b) {
    asm("fma.rn.f32x2 %0, %1, %2, %0;" : "+l"(d) : "l"(a), "l"(b));
}
__device__ __forceinline__ u64 addf2(u64 a, u64 b) {
    u64 r; asm("add.rn.f32x2 %0, %1, %2;" : "=l"(r) : "l"(a), "l"(b)); return r;
}
__device__ __forceinline__ float2 up2(u64 v) {
    float2 f; asm("mov.b64 {%0, %1}, %2;" : "=f"(f.x), "=f"(f.y) : "l"(v)); return f;
}
__device__ __forceinline__ float4 unpack_acc(u64 lo, u64 hi) {
    float2 a = up2(lo), b = up2(hi);
    return make_float4(a.x, a.y, b.x, b.y);
}
__device__ __forceinline__ float4 add4(float4 a, float4 b) {
    return make_float4(a.x + b.x, a.y + b.y, a.z + b.z, a.w + b.w);
}

#define LN2I 1.442695041f

// ---------------- transpose all 7 weights ----------------
__global__ void transpose_all(const float* __restrict__ s0, const float* __restrict__ s1,
                              const float* __restrict__ s2, const float* __restrict__ s3,
                              const float* __restrict__ s4, const float* __restrict__ s5,
                              const float* __restrict__ s6, float* __restrict__ dst) {
    const float* srcs[7] = {s0, s1, s2, s3, s4, s5, s6};
    __shared__ float t[16][17];
    const float* W = srcs[blockIdx.z];
    float* Wt = dst + (size_t)blockIdx.z * Dx * Dx;
    int bx = blockIdx.x * 16, by = blockIdx.y * 16;
    int x = threadIdx.x, y = threadIdx.y;
    t[y][x] = W[(by + y) * Dx + bx + x];
    __syncthreads();
    Wt[(bx + y) * Dx + by + x] = t[x][y];
}

// ---------------- K-chunk partial, R rows, NKP chunks of 128/NKP K-values ----------------
template<int R, int NKP>
__device__ __forceinline__ void gemm_partT(const float4* __restrict__ X4,
                                           const float* __restrict__ Wt,
                                           int kp, int lane, float4* out) {
    constexpr int CI = 32 / NKP;
    u64 aL[R], aH[R];
#pragma unroll
    for (int r = 0; r < R; r++) { aL[r] = 0ull; aH[r] = 0ull; }
    const ulonglong2* W2 = (const ulonglong2*)(Wt + kp * (Dx / NKP) * Dx);
#pragma unroll
    for (int c = 0; c < CI; c++) {
        ulonglong2 w0 = W2[(4 * c + 0) * 32 + lane];
        ulonglong2 w1 = W2[(4 * c + 1) * 32 + lane];
        ulonglong2 w2 = W2[(4 * c + 2) * 32 + lane];
        ulonglong2 w3 = W2[(4 * c + 3) * 32 + lane];
#pragma unroll
        for (int r = 0; r < R; r++) {
            float4 xv = X4[r * 32 + kp * CI + c];
            u64 p0 = pk2(xv.x), p1 = pk2(xv.y), p2 = pk2(xv.z), p3 = pk2(xv.w);
            ffma2(aL[r], p0, w0.x); ffma2(aH[r], p0, w0.y);
            ffma2(aL[r], p1, w1.x); ffma2(aH[r], p1, w1.y);
            ffma2(aL[r], p2, w2.x); ffma2(aH[r], p2, w2.y);
            ffma2(aL[r], p3, w3.x); ffma2(aH[r], p3, w3.y);
        }
    }
#pragma unroll
    for (int r = 0; r < R; r++) out[r] = unpack_acc(aL[r], aH[r]);
}

// ---------------- LN over a float4-per-lane row ----------------
__device__ __forceinline__ float4 ln_row(float4 hv, const float4& g4, const float4& b4) {
    float s = hv.x + hv.y + hv.z + hv.w;
    s = warp_sum(s);
    float mean = s * 0.0078125f;
    float4 dv = {hv.x - mean, hv.y - mean, hv.z - mean, hv.w - mean};
    float vs = dv.x * dv.x + dv.y * dv.y + dv.z * dv.z + dv.w * dv.w;
    vs = warp_sum(vs);
    float rstd = rsqrtf(vs * 0.0078125f + 1e-5f);
    float4 o = {dv.x * rstd * g4.x + b4.x, dv.y * rstd * g4.y + b4.y,
                dv.z * rstd * g4.z + b4.z, dv.w * rstd * g4.w + b4.w};
    return o;
}

// ---------------- projections: Q1, V1, K4, Q4 ----------------
__global__ void proj_batch(const float* __restrict__ q_emb, const float* __restrict__ s_emb,
                           const float* __restrict__ know, const float* __restrict__ WT,
                           const float* __restrict__ bq1, const float* __restrict__ bv1,
                           const float* __restrict__ bk4, const float* __restrict__ bq4,
                           float* __restrict__ Q1, float* __restrict__ V1,
                           float* __restrict__ K4, float* __restrict__ Q4) {
    const float* A; const float* Wt; const float* bias; float* C; int M;
    switch (blockIdx.y) {
        case 0:  A = q_emb; Wt = WT + 0 * 16384; bias = bq1; C = Q1; M = 1024; break;
        case 1:  A = s_emb; Wt = WT + 1 * 16384; bias = bv1; C = V1; M = 1024; break;
        case 2:  A = q_emb; Wt = WT + 4 * 16384; bias = bk4; C = K4; M = 1024; break;
        default: A = know;  Wt = WT + 3 * 16384; bias = bq4; C = Q4; M = 16;   break;
    }
    int row0 = blockIdx.x * 16;
    if (row0 >= M) return;
    __shared__ float4 Ps[16][4][32];
    int lane = threadIdx.x & 31, warp = threadIdx.x >> 5;
    int rg = warp >> 2, kp = warp & 3;
    float4 out[4];
    gemm_partT<4, 4>((const float4*)A + (size_t)(row0 + rg * 4) * 32, Wt, kp, lane, out);
#pragma unroll
    for (int r = 0; r < 4; r++) Ps[rg * 4 + r][kp][lane] = out[r];
    __syncthreads();
    float4 s = add4(add4(Ps[warp][0][lane], Ps[warp][1][lane]),
                    add4(Ps[warp][2][lane], Ps[warp][3][lane]));
    float4 b4 = ((const float4*)bias)[lane];
    ((float4*)C)[(size_t)(row0 + warp) * 32 + lane] = add4(s, b4);
}

// ---------------- block1 O-proj + residual + LN fused with V4 projection ----------------
__global__ void __launch_bounds__(256) oproj_ln1_v4(
        const float* __restrict__ X, const float* __restrict__ WoT,
        const float* __restrict__ bo, const float* __restrict__ res,
        const float* __restrict__ lng, const float* __restrict__ lnb,
        const float* __restrict__ WvT, const float* __restrict__ bv,
        float* __restrict__ v4) {
    __shared__ float4 Ps[4][8][32];
    __shared__ float4 p_sm[4][32];
    int lane = threadIdx.x & 31, warp = threadIdx.x >> 5;
    int row0 = blockIdx.x * 4;
    {
        float4 out[4];
        gemm_partT<4, 8>((const float4*)X + (size_t)row0 * 32, WoT, warp, lane, out);
#pragma unroll
        for (int r = 0; r < 4; r++) Ps[r][warp][lane] = out[r];
    }
    __syncthreads();
    if (warp < 4) {
        float4 s = Ps[warp][0][lane];
#pragma unroll
        for (int k = 1; k < 8; k++) s = add4(s, Ps[warp][k][lane]);
        float4 bb = ((const float4*)bo)[lane];
        float4 rv = ((const float4*)res)[(size_t)(row0 + warp) * 32 + lane];
        float4 hv = {s.x + bb.x + rv.x, s.y + bb.y + rv.y,
                     s.z + bb.z + rv.z, s.w + bb.w + rv.w};
        float4 g4 = ((const float4*)lng)[lane];
        float4 b4 = ((const float4*)lnb)[lane];
        p_sm[warp][lane] = ln_row(hv, g4, b4);
    }
    __syncthreads();
    {
        float4 out[4];
        gemm_partT<4, 8>((const float4*)p_sm[0], WvT, warp, lane, out);
#pragma unroll
        for (int r = 0; r < 4; r++) Ps[r][warp][lane] = out[r];
    }
    __syncthreads();
    if (warp < 4) {
        float4 s = Ps[warp][0][lane];
#pragma unroll
        for (int k = 1; k < 8; k++) s = add4(s, Ps[warp][k][lane]);
        float4 b4 = ((const float4*)bv)[lane];
        ((float4*)v4)[(size_t)(row0 + warp) * 32 + lane] = add4(s, b4);
    }
}

// ---------------- block4 O-proj + residual(know) + LN + scatter: 8 rows/block ----------------
__global__ void __launch_bounds__(128) oproj_ln4_k(
        const float* __restrict__ X, const float* __restrict__ WoT,
        const float* __restrict__ bo, const float* __restrict__ know,
        const float* __restrict__ lng, const float* __restrict__ lnb,
        float* __restrict__ z) {
    __shared__ float4 Ps[8][4][32];
    int lane = threadIdx.x & 31, warp = threadIdx.x >> 5;   // 4 warps = kp
    int row0 = blockIdx.x * 8;
    {
        float4 out[8];
        gemm_partT<8, 4>((const float4*)X + (size_t)row0 * 32, WoT, warp, lane, out);
#pragma unroll
        for (int r = 0; r < 8; r++) Ps[r][warp][lane] = out[r];
    }
    __syncthreads();
#pragma unroll
    for (int rr = 0; rr < 2; rr++) {
        int lrow = warp * 2 + rr;
        int row = row0 + lrow;                   // (b*NK+n)*S + s
        int bn = row >> 8, s = row & 255;
        int b = bn >> 4, n = bn & 15;
        float4 sm = add4(add4(Ps[lrow][0][lane], Ps[lrow][1][lane]),
                         add4(Ps[lrow][2][lane], Ps[lrow][3][lane]));
        float4 bb = ((const float4*)bo)[lane];
        float4 rv = ((const float4*)know)[n * 32 + lane];
        float4 hv = {sm.x + bb.x + rv.x, sm.y + bb.y + rv.y,
                     sm.z + bb.z + rv.z, sm.w + bb.w + rv.w};
        float4 g4 = ((const float4*)lng)[lane];
        float4 b4 = ((const float4*)lnb)[lane];
        ((float4*)z)[(((size_t)(b * Sx + s) * NKx) + n) * 32 + lane] = ln_row(hv, g4, b4);
    }
}

// ---------------- block1 attention: warp-per-row, packed PV ----------------
__global__ void attn1_kernel(const float* __restrict__ QK, const float* __restrict__ Vg,
                             const float* __restrict__ gamma,
                             float* __restrict__ q_scores, float* __restrict__ cat1) {
    __shared__ float Kd[DKx * Sx];   // [d][j]
    __shared__ float Vsh[Sx * DKx];  // [j][d]
    __shared__ float Psh[8][Sx];
    const int b = blockIdx.z, h = blockIdx.y;
    const int tid = threadIdx.x, lane = tid & 31, warp = tid >> 5;

    {
        const float* base = QK + ((size_t)b * Sx) * Dx + h * DKx;
        const float4* r = (const float4*)(base + (size_t)tid * Dx);
        float4 a0 = r[0], a1 = r[1], a2 = r[2], a3 = r[3];
        Kd[0*Sx+tid]=a0.x; Kd[1*Sx+tid]=a0.y; Kd[2*Sx+tid]=a0.z; Kd[3*Sx+tid]=a0.w;
        Kd[4*Sx+tid]=a1.x; Kd[5*Sx+tid]=a1.y; Kd[6*Sx+tid]=a1.z; Kd[7*Sx+tid]=a1.w;
        Kd[8*Sx+tid]=a2.x; Kd[9*Sx+tid]=a2.y; Kd[10*Sx+tid]=a2.z; Kd[11*Sx+tid]=a2.w;
        Kd[12*Sx+tid]=a3.x; Kd[13*Sx+tid]=a3.y; Kd[14*Sx+tid]=a3.z; Kd[15*Sx+tid]=a3.w;
    }
    {
        const float* base = Vg + ((size_t)b * Sx) * Dx + h * DKx;
        for (int idx = tid; idx < Sx * DKx; idx += 256) {
            int j = idx >> 4, d = idx & 15;
            Vsh[idx] = base[(size_t)j * Dx + d];
        }
    }
    __syncthreads();

    const float g2 = -fabsf(gamma[h]) * LN2I;
    const int i = blockIdx.x * 8 + warp;

    float q[16];
#pragma unroll
    for (int d = 0; d < 16; d++) q[d] = Kd[d * Sx + i];

    float sc2[8], ex[8];
    float sum = 0.f;
#pragma unroll
    for (int u = 0; u < 8; u++) {
        int j = u * 32 + lane;
        float s = 0.f;
#pragma unroll
        for (int d = 0; d < 16; d++) s = fmaf(q[d], Kd[d * Sx + j], s);
        sc2[u] = s * (0.25f * LN2I);
        float e = (j <= i) ? ex2_ap(sc2[u]) : 0.f;
        ex[u] = e;
        sum += e;
    }
    sum = warp_sum(sum);
    float inv = rcp_ap(sum);

    float cum[8]; float carry = 0.f;
#pragma unroll
    for (int u = 0; u < 8; u++) {
        float x = ex[u] * inv;
#pragma unroll
        for (int off = 1; off < 32; off <<= 1) {
            float nv = __shfl_up_sync(0xffffffffu, x, off);
            x += (lane >= off) ? nv : 0.f;
        }
        float seg = __shfl_sync(0xffffffffu, x, 31);
        cum[u] = x + carry;
        carry += seg;
    }
    const float total = carry;
    const float fi = (float)i;

    float sum2 = 0.f;
#pragma unroll
    for (int u = 0; u < 8; u++) {
        int j = u * 32 + lane;
        float pos = fabsf((float)j - fi);
        float dist = sqrt_ap(fmaxf((total - cum[u]) * pos, 0.f));
        float eff = ex2_ap(g2 * dist);
        float e2 = (j <= i) ? ex2_ap(sc2[u] * eff) : 0.f;
        ex[u] = e2;
        sum2 += e2;
    }
    sum2 = warp_sum(sum2);
    float inv2 = rcp_ap(sum2);

#pragma unroll
    for (int u = 0; u < 8; u++)
        Psh[warp][u * 32 + lane] = ex[u] * inv2;
    __syncwarp();

    {
        const float4* P4 = (const float4*)Psh[warp];
        float4* qs4 = (float4*)(q_scores + (((size_t)(b * Hx + h)) * Sx + i) * Sx);
        qs4[lane] = P4[lane];
        qs4[32 + lane] = P4[32 + lane];
    }

    const int jq = lane >> 3, dp = lane & 7;
    u64 acc = 0ull;
    const int njj = (i + 4) >> 2;
    const float* Pr = Psh[warp];
    for (int jj = 0; jj < njj; jj++) {
        int j = jj * 4 + jq;
        u64 v2 = *(const u64*)(Vsh + j * DKx + dp * 2);
        u64 p = pk2(Pr[j]);
        ffma2(acc, p, v2);
    }
    acc = addf2(acc, __shfl_xor_sync(0xffffffffu, acc, 8));
    acc = addf2(acc, __shfl_xor_sync(0xffffffffu, acc, 16));
    if (lane < 8) {
        float2 r = up2(acc);
        *(float2*)(cat1 + (((size_t)b * Sx) + i) * Dx + h * DKx + dp * 2) = r;
    }
}

// ---------------- block4 attention phase 1: softmax+decay+maxout -> ks_out ----------------
// grid (64 bn, 8 h, 2 iz), 256 thr; warp handles 16 rows (increasing i)
__global__ void attn4_p1(const float* __restrict__ q4g, const float* __restrict__ k4g,
                         const float* __restrict__ gamma, float* __restrict__ ks_out) {
    __shared__ float sc2sh[Sx];
    __shared__ float Csh[Sx];
    __shared__ float Psh[8][Sx];
    __shared__ float redA[8], redB[8];

    const int bn = blockIdx.x, h = blockIdx.y, iz = blockIdx.z;
    const int b = bn >> 4, n = bn & 15;
    const int tid = threadIdx.x, lane = tid & 31, warp = tid >> 5;

    {   // base score row (log2-scaled) + block max + prefix sums of exp
        const float* qp = q4g + n * Dx + h * DKx;
        const float* kp = k4g + ((size_t)b * Sx + tid) * Dx + h * DKx;
        float s = 0.f;
#pragma unroll
        for (int d = 0; d < 16; d++) s = fmaf(qp[d], kp[d], s);
        float v = s * (0.25f * LN2I);
        sc2sh[tid] = v;
        float m = warp_max(v);
        if (lane == 0) redA[warp] = m;
        __syncthreads();
        float M = redA[0];
#pragma unroll
        for (int w = 1; w < 8; w++) M = fmaxf(M, redA[w]);
        float x = ex2_ap(v - M);
#pragma unroll
        for (int off = 1; off < 32; off <<= 1) {
            float nv = __shfl_up_sync(0xffffffffu, x, off);
            x += (lane >= off) ? nv : 0.f;
        }
        if (lane == 31) redB[warp] = x;
        __syncthreads();
        float carry = 0.f;
#pragma unroll
        for (int w = 0; w < 7; w++) carry += (w < warp) ? redB[w] : 0.f;
        Csh[tid] = x + carry;
    }
    // zero this warp's P row buffer once; tail stays zero (uMax non-decreasing in t)
    ((float4*)Psh[warp])[lane] = make_float4(0.f, 0.f, 0.f, 0.f);
    ((float4*)Psh[warp])[32 + lane] = make_float4(0.f, 0.f, 0.f, 0.f);
    __syncthreads();

    const float g2 = -fabsf(gamma[h]) * LN2I;

    for (int t = 0; t < 16; ++t) {
        const int i = iz * 128 + 8 * t + warp;
        const int uMax = (i - 1) >> 5;
        const float invC = (i > 0) ? rcp_ap(Csh[i - 1]) : 0.f;
        const float fi = (float)i;

        float sum = 0.f, emax = 0.f;
        for (int u = 0; u <= uMax; u++) {
            int j = u * 32 + lane;
            float tt = fmaf(-Csh[j], invC, 1.0f);
            float pos = fabsf((float)j - fi);
            float dist = sqrt_ap(fmaxf(tt * pos, 0.f));
            float eff = ex2_ap(g2 * dist);
            float ev = ex2_ap(sc2sh[j] * eff);
            ev = (j < i) ? ev : 0.f;
            sum += ev;
            emax = fmaxf(emax, ev);
            Psh[warp][j] = ev;
        }
        sum = warp_sum(sum);
        emax = warp_max(emax);
        float m = fminf(rcp_ap(fmaxf(emax, 1e-30f)),
                        5.f * rcp_ap(fmaxf(sum, 1e-30f)));
        __syncwarp();

        const float4* P4 = (const float4*)Psh[warp];
        float4 v0 = P4[lane], v1 = P4[32 + lane];
        v0.x *= m; v0.y *= m; v0.z *= m; v0.w *= m;
        v1.x *= m; v1.y *= m; v1.z *= m; v1.w *= m;
        float4* ks4 = (float4*)(ks_out + ((((size_t)(b * Hx + h) * Sx + i) * NKx + n) << 8));
        ks4[lane] = v0;
        ks4[32 + lane] = v1;
        __syncwarp();
    }
}

// ---------------- block4 attention phase 2: cat4 = ks @ V ----------------
// grid (64 bn, 8 h), 256 thr; warp handles 32 rows in (i, i+8) pairs
__global__ void attn4_p2(const float* __restrict__ ks_out, const float* __restrict__ v4g,
                         float* __restrict__ cat4) {
    __shared__ float Vsh[Sx * DKx];     // 16KB
    __shared__ float Psh[8][2][Sx];     // 16KB
    const int bn = blockIdx.x, h = blockIdx.y;
    const int b = bn >> 4, n = bn & 15;
    const int tid = threadIdx.x, lane = tid & 31, warp = tid >> 5;

    {
        const float* vb = v4g + ((size_t)b * Sx) * Dx + h * DKx;
        for (int idx = tid; idx < Sx * DKx; idx += 256) {
            int j = idx >> 4, d = idx & 15;
            Vsh[idx] = vb[(size_t)j * Dx + d];
        }
    }
    __syncthreads();

    const int jq = lane >> 3, dp = lane & 7;

    for (int gb = 0; gb < 16; ++gb) {
        const int i1 = warp + 8 * (2 * gb + 1);

#pragma unroll
        for (int k = 0; k < 2; ++k) {
            const int i = i1 - 8 + 8 * k;
            const float4* src = (const float4*)(ks_out +
                ((((size_t)(b * Hx + h) * Sx + i) * NKx + n) << 8));
            float4* dst = (float4*)Psh[warp][k];
            dst[lane] = src[lane];
            dst[32 + lane] = src[32 + lane];
        }
        __syncwarp();

        u64 a0 = 0ull, a1 = 0ull;
        const int njj = (i1 + 3) >> 2;        // ks rows are zero beyond i
        const float* Pr0 = Psh[warp][0];
        const float* Pr1 = Psh[warp][1];
        for (int jj = 0; jj < njj; jj++) {
            int j = jj * 4 + jq;
            u64 v2 = *(const u64*)(Vsh + j * DKx + dp * 2);
            ffma2(a0, pk2(Pr0[j]), v2);
            ffma2(a1, pk2(Pr1[j]), v2);
        }
        a0 = addf2(a0, __shfl_xor_sync(0xffffffffu, a0, 8));
        a0 = addf2(a0, __shfl_xor_sync(0xffffffffu, a0, 16));
        a1 = addf2(a1, __shfl_xor_sync(0xffffffffu, a1, 8));
        a1 = addf2(a1, __shfl_xor_sync(0xffffffffu, a1, 16));
        if (lane < 8) {
            int i0 = i1 - 8;
            float2 r0 = up2(a0), r1 = up2(a1);
            *(float2*)(cat4 + ((size_t)bn * Sx + i0) * Dx + h * DKx + dp * 2) = r0;
            *(float2*)(cat4 + ((size_t)bn * Sx + i1) * Dx + h * DKx + dp * 2) = r1;
        }
        __syncwarp();
    }
}

// ---------------- launch ----------------
extern "C" void kernel_launch(void* const* d_in, const int* in_sizes, int n_in,
                              void* d_out, int out_size) {
    (void)in_sizes; (void)n_in; (void)out_size;
    const float* q_emb  = (const float*)d_in[0];
    const float* s_emb  = (const float*)d_in[1];
    const float* b1_Wq  = (const float*)d_in[3];
    const float* b1_bq  = (const float*)d_in[4];
    const float* b1_Wv  = (const float*)d_in[5];
    const float* b1_bv  = (const float*)d_in[6];
    const float* b1_Wo  = (const float*)d_in[7];
    const float* b1_bo  = (const float*)d_in[8];
    const float* b1_gam = (const float*)d_in[9];
    const float* b1_lng = (const float*)d_in[10];
    const float* b1_lnb = (const float*)d_in[11];
    const float* b4_Wq  = (const float*)d_in[12];
    const float* b4_bq  = (const float*)d_in[13];
    const float* b4_Wk  = (const float*)d_in[14];
    const float* b4_bk  = (const float*)d_in[15];
    const float* b4_Wv  = (const float*)d_in[16];
    const float* b4_bv  = (const float*)d_in[17];
    const float* b4_Wo  = (const float*)d_in[18];
    const float* b4_bo  = (const float*)d_in[19];
    const float* b4_gam = (const float*)d_in[20];
    const float* b4_lng = (const float*)d_in[21];
    const float* b4_lnb = (const float*)d_in[22];
    const float* know   = (const float*)d_in[23];

    float* z_out  = (float*)d_out;
    float* qs_out = z_out + (size_t)BSx * Sx * NKx * Dx;
    float* ks_out = qs_out + (size_t)BSx * Hx * Sx * Sx;

    float *Q1, *V1, *cat1, *q4, *k4, *v4, *cat4, *WT;
    cudaGetSymbolAddress((void**)&Q1,   d_Q1);
    cudaGetSymbolAddress((void**)&V1,   d_V1);
    cudaGetSymbolAddress((void**)&cat1, d_cat1);
    cudaGetSymbolAddress((void**)&q4,   d_q4);
    cudaGetSymbolAddress((void**)&k4,   d_k4);
    cudaGetSymbolAddress((void**)&v4,   d_v4);
    cudaGetSymbolAddress((void**)&cat4, d_cat4);
    cudaGetSymbolAddress((void**)&WT,   d_WT);

    transpose_all<<<dim3(8, 8, 7), dim3(16, 16)>>>(b1_Wq, b1_Wv, b1_Wo, b4_Wq, b4_Wk, b4_Wv, b4_Wo, WT);

    proj_batch<<<dim3(64, 4), 512>>>(q_emb, s_emb, know, WT,
                                     b1_bq, b1_bv, b4_bk, b4_bq,
                                     Q1, V1, k4, q4);

    attn1_kernel<<<dim3(Sx / 8, Hx, BSx), 256>>>(Q1, V1, b1_gam, qs_out, cat1);

    // launch slot 3 -> profiled next round
    attn4_p1<<<dim3(BSx * NKx, Hx, 2), 256>>>(q4, k4, b4_gam, ks_out);

    oproj_ln1_v4<<<256, 256>>>(cat1, WT + 2 * 16384, b1_bo, q_emb, b1_lng, b1_lnb,
                               WT + 5 * 16384, b4_bv, v4);

    attn4_p2<<<dim3(BSx * NKx, Hx), 256>>>(ks_out, v4, cat4);

    oproj_ln4_k<<<2048, 128>>>(cat4, WT + 6 * 16384, b4_bo, know, b4_lng, b4_lnb, z_out);
}

// round 12
// speedup vs baseline: 1.8455x; 1.8455x over previous
#include <cuda_runtime.h>
#include <math.h>
#include <stdint.h>

#define Sx   256
#define Dx   128
#define Hx   8
#define DKx  16
#define NKx  16
#define BSx  4

typedef unsigned long long u64;

// ---------------- scratch ----------------
__device__ float d_Q1[BSx * Sx * Dx];
__device__ float d_V1[BSx * Sx * Dx];
__device__ float d_cat1[BSx * Sx * Dx];
__device__ float d_q4[NKx * Dx];
__device__ float d_k4[BSx * Sx * Dx];
__device__ float d_v4[BSx * Sx * Dx];
__device__ float d_cat4[BSx * NKx * Sx * Dx];
__device__ float d_WT[7][Dx * Dx];

// ---------------- helpers ----------------
__device__ __forceinline__ float warp_max(float v) {
#pragma unroll
    for (int o = 16; o; o >>= 1) v = fmaxf(v, __shfl_xor_sync(0xffffffffu, v, o));
    return v;
}
__device__ __forceinline__ float warp_sum(float v) {
#pragma unroll
    for (int o = 16; o; o >>= 1) v += __shfl_xor_sync(0xffffffffu, v, o);
    return v;
}
__device__ __forceinline__ float rcp_ap(float x) {
    float r; asm("rcp.approx.f32 %0, %1;" : "=f"(r) : "f"(x)); return r;
}
__device__ __forceinline__ float sqrt_ap(float x) {
    float r; asm("sqrt.approx.f32 %0, %1;" : "=f"(r) : "f"(x)); return r;
}
__device__ __forceinline__ float ex2_ap(float x) {
    float r; asm("ex2.approx.f32 %0, %1;" : "=f"(r) : "f"(x)); return r;
}
__device__ __forceinline__ u64 pk2(float x) {
    u64 r; asm("mov.b64 %0, {%1, %1};" : "=l"(r) : "f"(x)); return r;
}
__device__ __forceinline__ void ffma2(u64& d, u64 a, u64 b) {
    asm("fma.rn.f32x2 %0, %1, %2, %0;" : "+l"(d) : "l"(a), "l"(b));
}
__device__ __forceinline__ u64 addf2(u64 a, u64 b) {
    u64 r; asm("add.rn.f32x2 %0, %1, %2;" : "=l"(r) : "l"(a), "l"(b)); return r;
}
__device__ __forceinline__ u64 mulf2(u64 a, u64 b) {
    u64 r; asm("mul.rn.f32x2 %0, %1, %2;" : "=l"(r) : "l"(a), "l"(b)); return r;
}
__device__ __forceinline__ float2 up2(u64 v) {
    float2 f; asm("mov.b64 {%0, %1}, %2;" : "=f"(f.x), "=f"(f.y) : "l"(v)); return f;
}
__device__ __forceinline__ float4 unpack_acc(u64 lo, u64 hi) {
    float2 a = up2(lo), b = up2(hi);
    return make_float4(a.x, a.y, b.x, b.y);
}
__device__ __forceinline__ float4 add4(float4 a, float4 b) {
    return make_float4(a.x + b.x, a.y + b.y, a.z + b.z, a.w + b.w);
}

#define LN2I 1.442695041f

// ---------------- transpose all 7 weights ----------------
__global__ void transpose_all(const float* __restrict__ s0, const float* __restrict__ s1,
                              const float* __restrict__ s2, const float* __restrict__ s3,
                              const float* __restrict__ s4, const float* __restrict__ s5,
                              const float* __restrict__ s6, float* __restrict__ dst) {
    const float* srcs[7] = {s0, s1, s2, s3, s4, s5, s6};
    __shared__ float t[16][17];
    const float* W = srcs[blockIdx.z];
    float* Wt = dst + (size_t)blockIdx.z * Dx * Dx;
    int bx = blockIdx.x * 16, by = blockIdx.y * 16;
    int x = threadIdx.x, y = threadIdx.y;
    t[y][x] = W[(by + y) * Dx + bx + x];
    __syncthreads();
    Wt[(bx + y) * Dx + by + x] = t[x][y];
}

// ---------------- K-chunk partial, R rows, NKP chunks of 128/NKP K-values ----------------
template<int R, int NKP>
__device__ __forceinline__ void gemm_partT(const float4* __restrict__ X4,
                                           const float* __restrict__ Wt,
                                           int kp, int lane, float4* out) {
    constexpr int CI = 32 / NKP;
    u64 aL[R], aH[R];
#pragma unroll
    for (int r = 0; r < R; r++) { aL[r] = 0ull; aH[r] = 0ull; }
    const ulonglong2* W2 = (const ulonglong2*)(Wt + kp * (Dx / NKP) * Dx);
#pragma unroll
    for (int c = 0; c < CI; c++) {
        ulonglong2 w0 = W2[(4 * c + 0) * 32 + lane];
        ulonglong2 w1 = W2[(4 * c + 1) * 32 + lane];
        ulonglong2 w2 = W2[(4 * c + 2) * 32 + lane];
        ulonglong2 w3 = W2[(4 * c + 3) * 32 + lane];
#pragma unroll
        for (int r = 0; r < R; r++) {
            float4 xv = X4[r * 32 + kp * CI + c];
            u64 p0 = pk2(xv.x), p1 = pk2(xv.y), p2 = pk2(xv.z), p3 = pk2(xv.w);
            ffma2(aL[r], p0, w0.x); ffma2(aH[r], p0, w0.y);
            ffma2(aL[r], p1, w1.x); ffma2(aH[r], p1, w1.y);
            ffma2(aL[r], p2, w2.x); ffma2(aH[r], p2, w2.y);
            ffma2(aL[r], p3, w3.x); ffma2(aH[r], p3, w3.y);
        }
    }
#pragma unroll
    for (int r = 0; r < R; r++) out[r] = unpack_acc(aL[r], aH[r]);
}

// ---------------- LN over a float4-per-lane row ----------------
__device__ __forceinline__ float4 ln_row(float4 hv, const float4& g4, const float4& b4) {
    float s = hv.x + hv.y + hv.z + hv.w;
    s = warp_sum(s);
    float mean = s * 0.0078125f;
    float4 dv = {hv.x - mean, hv.y - mean, hv.z - mean, hv.w - mean};
    float vs = dv.x * dv.x + dv.y * dv.y + dv.z * dv.z + dv.w * dv.w;
    vs = warp_sum(vs);
    float rstd = rsqrtf(vs * 0.0078125f + 1e-5f);
    float4 o = {dv.x * rstd * g4.x + b4.x, dv.y * rstd * g4.y + b4.y,
                dv.z * rstd * g4.z + b4.z, dv.w * rstd * g4.w + b4.w};
    return o;
}

// ---------------- projections: Q1, V1, K4, Q4 ----------------
__global__ void proj_batch(const float* __restrict__ q_emb, const float* __restrict__ s_emb,
                           const float* __restrict__ know, const float* __restrict__ WT,
                           const float* __restrict__ bq1, const float* __restrict__ bv1,
                           const float* __restrict__ bk4, const float* __restrict__ bq4,
                           float* __restrict__ Q1, float* __restrict__ V1,
                           float* __restrict__ K4, float* __restrict__ Q4) {
    const float* A; const float* Wt; const float* bias; float* C; int M;
    switch (blockIdx.y) {
        case 0:  A = q_emb; Wt = WT + 0 * 16384; bias = bq1; C = Q1; M = 1024; break;
        case 1:  A = s_emb; Wt = WT + 1 * 16384; bias = bv1; C = V1; M = 1024; break;
        case 2:  A = q_emb; Wt = WT + 4 * 16384; bias = bk4; C = K4; M = 1024; break;
        default: A = know;  Wt = WT + 3 * 16384; bias = bq4; C = Q4; M = 16;   break;
    }
    int row0 = blockIdx.x * 16;
    if (row0 >= M) return;
    __shared__ float4 Ps[16][4][32];
    int lane = threadIdx.x & 31, warp = threadIdx.x >> 5;
    int rg = warp >> 2, kp = warp & 3;
    float4 out[4];
    gemm_partT<4, 4>((const float4*)A + (size_t)(row0 + rg * 4) * 32, Wt, kp, lane, out);
#pragma unroll
    for (int r = 0; r < 4; r++) Ps[rg * 4 + r][kp][lane] = out[r];
    __syncthreads();
    float4 s = add4(add4(Ps[warp][0][lane], Ps[warp][1][lane]),
                    add4(Ps[warp][2][lane], Ps[warp][3][lane]));
    float4 b4 = ((const float4*)bias)[lane];
    ((float4*)C)[(size_t)(row0 + warp) * 32 + lane] = add4(s, b4);
}

// ---------------- block1 O-proj + residual + LN fused with V4 projection ----------------
__global__ void __launch_bounds__(256) oproj_ln1_v4(
        const float* __restrict__ X, const float* __restrict__ WoT,
        const float* __restrict__ bo, const float* __restrict__ res,
        const float* __restrict__ lng, const float* __restrict__ lnb,
        const float* __restrict__ WvT, const float* __restrict__ bv,
        float* __restrict__ v4) {
    __shared__ float4 Ps[4][8][32];
    __shared__ float4 p_sm[4][32];
    int lane = threadIdx.x & 31, warp = threadIdx.x >> 5;
    int row0 = blockIdx.x * 4;
    {
        float4 out[4];
        gemm_partT<4, 8>((const float4*)X + (size_t)row0 * 32, WoT, warp, lane, out);
#pragma unroll
        for (int r = 0; r < 4; r++) Ps[r][warp][lane] = out[r];
    }
    __syncthreads();
    if (warp < 4) {
        float4 s = Ps[warp][0][lane];
#pragma unroll
        for (int k = 1; k < 8; k++) s = add4(s, Ps[warp][k][lane]);
        float4 bb = ((const float4*)bo)[lane];
        float4 rv = ((const float4*)res)[(size_t)(row0 + warp) * 32 + lane];
        float4 hv = {s.x + bb.x + rv.x, s.y + bb.y + rv.y,
                     s.z + bb.z + rv.z, s.w + bb.w + rv.w};
        float4 g4 = ((const float4*)lng)[lane];
        float4 b4 = ((const float4*)lnb)[lane];
        p_sm[warp][lane] = ln_row(hv, g4, b4);
    }
    __syncthreads();
    {
        float4 out[4];
        gemm_partT<4, 8>((const float4*)p_sm[0], WvT, warp, lane, out);
#pragma unroll
        for (int r = 0; r < 4; r++) Ps[r][warp][lane] = out[r];
    }
    __syncthreads();
    if (warp < 4) {
        float4 s = Ps[warp][0][lane];
#pragma unroll
        for (int k = 1; k < 8; k++) s = add4(s, Ps[warp][k][lane]);
        float4 b4 = ((const float4*)bv)[lane];
        ((float4*)v4)[(size_t)(row0 + warp) * 32 + lane] = add4(s, b4);
    }
}

// ---------------- block4 O-proj + residual(know) + LN + scatter: 16 rows/block ----------------
__global__ void __launch_bounds__(128) oproj_ln4_k(
        const float* __restrict__ X, const float* __restrict__ WoT,
        const float* __restrict__ bo, const float* __restrict__ know,
        const float* __restrict__ lng, const float* __restrict__ lnb,
        float* __restrict__ z) {
    __shared__ float4 Ps[16][4][32];
    int lane = threadIdx.x & 31, warp = threadIdx.x >> 5;   // 4 warps = kp
    int row0 = blockIdx.x * 16;
    {
        float4 out[16];
        gemm_partT<16, 4>((const float4*)X + (size_t)row0 * 32, WoT, warp, lane, out);
#pragma unroll
        for (int r = 0; r < 16; r++) Ps[r][warp][lane] = out[r];
    }
    __syncthreads();
#pragma unroll
    for (int rr = 0; rr < 4; rr++) {
        int lrow = warp * 4 + rr;
        int row = row0 + lrow;
        int bn = row >> 8, s = row & 255;
        int b = bn >> 4, n = bn & 15;
        float4 sm = add4(add4(Ps[lrow][0][lane], Ps[lrow][1][lane]),
                         add4(Ps[lrow][2][lane], Ps[lrow][3][lane]));
        float4 bb = ((const float4*)bo)[lane];
        float4 rv = ((const float4*)know)[n * 32 + lane];
        float4 hv = {sm.x + bb.x + rv.x, sm.y + bb.y + rv.y,
                     sm.z + bb.z + rv.z, sm.w + bb.w + rv.w};
        float4 g4 = ((const float4*)lng)[lane];
        float4 b4 = ((const float4*)lnb)[lane];
        ((float4*)z)[(((size_t)(b * Sx + s) * NKx) + n) * 32 + lane] = ln_row(hv, g4, b4);
    }
}

// ---------------- block1 attention: warp-per-row, packed PV ----------------
__global__ void attn1_kernel(const float* __restrict__ QK, const float* __restrict__ Vg,
                             const float* __restrict__ gamma,
                             float* __restrict__ q_scores, float* __restrict__ cat1) {
    __shared__ float Kd[DKx * Sx];
    __shared__ float Vsh[Sx * DKx];
    __shared__ float Psh[8][Sx];
    const int b = blockIdx.z, h = blockIdx.y;
    const int tid = threadIdx.x, lane = tid & 31, warp = tid >> 5;

    {
        const float* base = QK + ((size_t)b * Sx) * Dx + h * DKx;
        const float4* r = (const float4*)(base + (size_t)tid * Dx);
        float4 a0 = r[0], a1 = r[1], a2 = r[2], a3 = r[3];
        Kd[0*Sx+tid]=a0.x; Kd[1*Sx+tid]=a0.y; Kd[2*Sx+tid]=a0.z; Kd[3*Sx+tid]=a0.w;
        Kd[4*Sx+tid]=a1.x; Kd[5*Sx+tid]=a1.y; Kd[6*Sx+tid]=a1.z; Kd[7*Sx+tid]=a1.w;
        Kd[8*Sx+tid]=a2.x; Kd[9*Sx+tid]=a2.y; Kd[10*Sx+tid]=a2.z; Kd[11*Sx+tid]=a2.w;
        Kd[12*Sx+tid]=a3.x; Kd[13*Sx+tid]=a3.y; Kd[14*Sx+tid]=a3.z; Kd[15*Sx+tid]=a3.w;
    }
    {
        const float* base = Vg + ((size_t)b * Sx) * Dx + h * DKx;
        for (int idx = tid; idx < Sx * DKx; idx += 256) {
            int j = idx >> 4, d = idx & 15;
            Vsh[idx] = base[(size_t)j * Dx + d];
        }
    }
    __syncthreads();

    const float g2 = -fabsf(gamma[h]) * LN2I;
    const int i = blockIdx.x * 8 + warp;

    float q[16];
#pragma unroll
    for (int d = 0; d < 16; d++) q[d] = Kd[d * Sx + i];

    float sc2[8], ex[8];
    float sum = 0.f;
#pragma unroll
    for (int u = 0; u < 8; u++) {
        int j = u * 32 + lane;
        float s = 0.f;
#pragma unroll
        for (int d = 0; d < 16; d++) s = fmaf(q[d], Kd[d * Sx + j], s);
        sc2[u] = s * (0.25f * LN2I);
        float e = (j <= i) ? ex2_ap(sc2[u]) : 0.f;
        ex[u] = e;
        sum += e;
    }
    sum = warp_sum(sum);
    float inv = rcp_ap(sum);

    float cum[8]; float carry = 0.f;
#pragma unroll
    for (int u = 0; u < 8; u++) {
        float x = ex[u] * inv;
#pragma unroll
        for (int off = 1; off < 32; off <<= 1) {
            float nv = __shfl_up_sync(0xffffffffu, x, off);
            x += (lane >= off) ? nv : 0.f;
        }
        float seg = __shfl_sync(0xffffffffu, x, 31);
        cum[u] = x + carry;
        carry += seg;
    }
    const float total = carry;
    const float fi = (float)i;

    float sum2 = 0.f;
#pragma unroll
    for (int u = 0; u < 8; u++) {
        int j = u * 32 + lane;
        float pos = fabsf((float)j - fi);
        float dist = sqrt_ap(fmaxf((total - cum[u]) * pos, 0.f));
        float eff = ex2_ap(g2 * dist);
        float e2 = (j <= i) ? ex2_ap(sc2[u] * eff) : 0.f;
        ex[u] = e2;
        sum2 += e2;
    }
    sum2 = warp_sum(sum2);
    float inv2 = rcp_ap(sum2);

#pragma unroll
    for (int u = 0; u < 8; u++)
        Psh[warp][u * 32 + lane] = ex[u] * inv2;
    __syncwarp();

    {
        const float4* P4 = (const float4*)Psh[warp];
        float4* qs4 = (float4*)(q_scores + (((size_t)(b * Hx + h)) * Sx + i) * Sx);
        qs4[lane] = P4[lane];
        qs4[32 + lane] = P4[32 + lane];
    }

    const int jq = lane >> 3, dp = lane & 7;
    u64 acc = 0ull;
    const int njj = (i + 4) >> 2;
    const float* Pr = Psh[warp];
    for (int jj = 0; jj < njj; jj++) {
        int j = jj * 4 + jq;
        u64 v2 = *(const u64*)(Vsh + j * DKx + dp * 2);
        u64 p = pk2(Pr[j]);
        ffma2(acc, p, v2);
    }
    acc = addf2(acc, __shfl_xor_sync(0xffffffffu, acc, 8));
    acc = addf2(acc, __shfl_xor_sync(0xffffffffu, acc, 16));
    if (lane < 8) {
        float2 r = up2(acc);
        *(float2*)(cat1 + (((size_t)b * Sx) + i) * Dx + h * DKx + dp * 2) = r;
    }
}

// ---------------- block4 attention: fused, register-cached softmax, packed PV ----------------
// grid (64 bn, 8 h, 2 iz), 256 thr; warp handles 16 rows in (i, i+8) pairs
__global__ void attn4_kernel(const float* __restrict__ q4g, const float* __restrict__ k4g,
                             const float* __restrict__ v4g, const float* __restrict__ gamma,
                             float* __restrict__ ks_out, float* __restrict__ cat4) {
    __shared__ float Vsh[Sx * DKx];     // 16KB
    __shared__ float sc2sh[Sx];
    __shared__ float Csh[Sx];
    __shared__ float Psh[8][2][Sx];     // 16KB
    __shared__ float redA[8], redB[8];

    const int bn = blockIdx.x, h = blockIdx.y, iz = blockIdx.z;
    const int b = bn >> 4, n = bn & 15;
    const int tid = threadIdx.x, lane = tid & 31, warp = tid >> 5;

    {
        const float* vb = v4g + ((size_t)b * Sx) * Dx + h * DKx;
        const int vlim = (iz ? Sx : 128) * DKx;
        for (int idx = tid; idx < vlim; idx += 256) {
            int j = idx >> 4, d = idx & 15;
            Vsh[idx] = vb[(size_t)j * Dx + d];
        }
    }
    {   // base score row (log2-scaled) + block max + prefix sums of exp
        const float* qp = q4g + n * Dx + h * DKx;
        const float* kp = k4g + ((size_t)b * Sx + tid) * Dx + h * DKx;
        float s = 0.f;
#pragma unroll
        for (int d = 0; d < 16; d++) s = fmaf(qp[d], kp[d], s);
        float v = s * (0.25f * LN2I);
        sc2sh[tid] = v;
        float m = warp_max(v);
        if (lane == 0) redA[warp] = m;
        __syncthreads();
        float M = redA[0];
#pragma unroll
        for (int w = 1; w < 8; w++) M = fmaxf(M, redA[w]);
        float x = ex2_ap(v - M);
#pragma unroll
        for (int off = 1; off < 32; off <<= 1) {
            float nv = __shfl_up_sync(0xffffffffu, x, off);
            x += (lane >= off) ? nv : 0.f;
        }
        if (lane == 31) redB[warp] = x;
        __syncthreads();
        float carry = 0.f;
#pragma unroll
        for (int w = 0; w < 7; w++) carry += (w < warp) ? redB[w] : 0.f;
        Csh[tid] = x + carry;
    }
    __syncthreads();

    // register caches
    float sc2[8], Cu[8], fj[8];
#pragma unroll
    for (int u = 0; u < 8; u++) {
        int j = u * 32 + lane;
        sc2[u] = sc2sh[j];
        Cu[u] = Csh[j];
        fj[u] = (float)j;
    }
    // zero both P row buffers once; processed i ascends so the tail stays valid
    ((float4*)Psh[warp][0])[lane] = make_float4(0.f, 0.f, 0.f, 0.f);
    ((float4*)Psh[warp][0])[32 + lane] = make_float4(0.f, 0.f, 0.f, 0.f);
    ((float4*)Psh[warp][1])[lane] = make_float4(0.f, 0.f, 0.f, 0.f);
    ((float4*)Psh[warp][1])[32 + lane] = make_float4(0.f, 0.f, 0.f, 0.f);
    __syncwarp();

    const float g2 = -fabsf(gamma[h]) * LN2I;
    const int jq = lane >> 3, dp = lane & 7;

    for (int gb = 0; gb < 8; ++gb) {
        const int i1 = iz * 128 + warp + 8 * (2 * gb + 1);
        float mlt[2];

#pragma unroll
        for (int k = 0; k < 2; ++k) {
            const int i = i1 - 8 + 8 * k;
            const int uMax = (i - 1) >> 5;
            const float invC = (i > 0) ? rcp_ap(Csh[i - 1]) : 0.f;
            const float fi = (float)i;

            float ev[8];
            float sum = 0.f, emax = 0.f;
#pragma unroll
            for (int u = 0; u < 8; u++) {
                if (u <= uMax) {
                    float t = fmaf(-Cu[u], invC, 1.0f);
                    float pos = fabsf(fj[u] - fi);
                    float dist = sqrt_ap(fmaxf(t * pos, 0.f));
                    float eff = ex2_ap(g2 * dist);
                    float e = ex2_ap(sc2[u] * eff);
                    e = (fj[u] < fi) ? e : 0.f;
                    ev[u] = e;
                    sum += e;
                    emax = fmaxf(emax, e);
                    Psh[warp][k][u * 32 + lane] = e;
                } else ev[u] = 0.f;
            }
            sum = warp_sum(sum);
            emax = warp_max(emax);
            float m = fminf(rcp_ap(fmaxf(emax, 1e-30f)),
                            5.f * rcp_ap(fmaxf(sum, 1e-30f)));
            mlt[k] = m;

            // direct coalesced ks stores from registers
            float* ks = ks_out + ((((size_t)(b * Hx + h) * Sx + i) * NKx + n) << 8);
#pragma unroll
            for (int u = 0; u < 8; u++)
                ks[u * 32 + lane] = ev[u] * m;
        }
        __syncwarp();

        // packed PV on raw e, deferred mult; V LDS shared across the row pair
        u64 a0 = 0ull, a1 = 0ull;
        const int njj = (i1 + 3) >> 2;       // Psh zero beyond i
        const float* Pr0 = Psh[warp][0];
        const float* Pr1 = Psh[warp][1];
        for (int jj = 0; jj < njj; jj++) {
            int j = jj * 4 + jq;
            u64 v2 = *(const u64*)(Vsh + j * DKx + dp * 2);
            ffma2(a0, pk2(Pr0[j]), v2);
            ffma2(a1, pk2(Pr1[j]), v2);
        }
        a0 = addf2(a0, __shfl_xor_sync(0xffffffffu, a0, 8));
        a0 = addf2(a0, __shfl_xor_sync(0xffffffffu, a0, 16));
        a1 = addf2(a1, __shfl_xor_sync(0xffffffffu, a1, 8));
        a1 = addf2(a1, __shfl_xor_sync(0xffffffffu, a1, 16));
        a0 = mulf2(a0, pk2(mlt[0]));
        a1 = mulf2(a1, pk2(mlt[1]));
        if (lane < 8) {
            int i0 = i1 - 8;
            float2 r0 = up2(a0), r1 = up2(a1);
            *(float2*)(cat4 + ((size_t)bn * Sx + i0) * Dx + h * DKx + dp * 2) = r0;
            *(float2*)(cat4 + ((size_t)bn * Sx + i1) * Dx + h * DKx + dp * 2) = r1;
        }
        __syncwarp();
    }
}

// ---------------- launch ----------------
extern "C" void kernel_launch(void* const* d_in, const int* in_sizes, int n_in,
                              void* d_out, int out_size) {
    (void)in_sizes; (void)n_in; (void)out_size;
    const float* q_emb  = (const float*)d_in[0];
    const float* s_emb  = (const float*)d_in[1];
    const float* b1_Wq  = (const float*)d_in[3];
    const float* b1_bq  = (const float*)d_in[4];
    const float* b1_Wv  = (const float*)d_in[5];
    const float* b1_bv  = (const float*)d_in[6];
    const float* b1_Wo  = (const float*)d_in[7];
    const float* b1_bo  = (const float*)d_in[8];
    const float* b1_gam = (const float*)d_in[9];
    const float* b1_lng = (const float*)d_in[10];
    const float* b1_lnb = (const float*)d_in[11];
    const float* b4_Wq  = (const float*)d_in[12];
    const float* b4_bq  = (const float*)d_in[13];
    const float* b4_Wk  = (const float*)d_in[14];
    const float* b4_bk  = (const float*)d_in[15];
    const float* b4_Wv  = (const float*)d_in[16];
    const float* b4_bv  = (const float*)d_in[17];
    const float* b4_Wo  = (const float*)d_in[18];
    const float* b4_bo  = (const float*)d_in[19];
    const float* b4_gam = (const float*)d_in[20];
    const float* b4_lng = (const float*)d_in[21];
    const float* b4_lnb = (const float*)d_in[22];
    const float* know   = (const float*)d_in[23];

    float* z_out  = (float*)d_out;
    float* qs_out = z_out + (size_t)BSx * Sx * NKx * Dx;
    float* ks_out = qs_out + (size_t)BSx * Hx * Sx * Sx;

    float *Q1, *V1, *cat1, *q4, *k4, *v4, *cat4, *WT;
    cudaGetSymbolAddress((void**)&Q1,   d_Q1);
    cudaGetSymbolAddress((void**)&V1,   d_V1);
    cudaGetSymbolAddress((void**)&cat1, d_cat1);
    cudaGetSymbolAddress((void**)&q4,   d_q4);
    cudaGetSymbolAddress((void**)&k4,   d_k4);
    cudaGetSymbolAddress((void**)&v4,   d_v4);
    cudaGetSymbolAddress((void**)&cat4, d_cat4);
    cudaGetSymbolAddress((void**)&WT,   d_WT);

    transpose_all<<<dim3(8, 8, 7), dim3(16, 16)>>>(b1_Wq, b1_Wv, b1_Wo, b4_Wq, b4_Wk, b4_Wv, b4_Wo, WT);

    proj_batch<<<dim3(64, 4), 512>>>(q_emb, s_emb, know, WT,
                                     b1_bq, b1_bv, b4_bk, b4_bq,
                                     Q1, V1, k4, q4);

    attn1_kernel<<<dim3(Sx / 8, Hx, BSx), 256>>>(Q1, V1, b1_gam, qs_out, cat1);

    oproj_ln1_v4<<<256, 256>>>(cat1, WT + 2 * 16384, b1_bo, q_emb, b1_lng, b1_lnb,
                               WT + 5 * 16384, b4_bv, v4);

    attn4_kernel<<<dim3(BSx * NKx, Hx, 2), 256>>>(q4, k4, v4, b4_gam, ks_out, cat4);

    oproj_ln4_k<<<1024, 128>>>(cat4, WT + 6 * 16384, b4_bo, know, b4_lng, b4_lnb, z_out);
}